// round 1
// baseline (speedup 1.0000x reference)
#include <cuda_runtime.h>
#include <math.h>
#include <math_constants.h>

#define B_SZ   2
#define S_LEN  2048
#define D_MOD  1024
#define NH     16
#define DK     64
#define M_TOT  (B_SZ * S_LEN)   // 4096

// Scratch (allocation-free rule: __device__ globals)
__device__ float g_Q[M_TOT * D_MOD];
__device__ float g_K[M_TOT * D_MOD];
__device__ float g_V[M_TOT * D_MOD];
__device__ float g_AO[M_TOT * D_MOD];

__device__ __forceinline__ unsigned f2tf(float f) {
    unsigned u;
    asm("cvt.rna.tf32.f32 %0, %1;" : "=r"(u) : "f"(f));
    return u;
}

__device__ __forceinline__ void mma8(float* d, const unsigned* a, const unsigned* b) {
    asm volatile(
        "mma.sync.aligned.m16n8k8.row.col.f32.tf32.tf32.f32 "
        "{%0,%1,%2,%3}, {%4,%5,%6,%7}, {%8,%9}, {%0,%1,%2,%3};\n"
        : "+f"(d[0]), "+f"(d[1]), "+f"(d[2]), "+f"(d[3])
        : "r"(a[0]), "r"(a[1]), "r"(a[2]), "r"(a[3]), "r"(b[0]), "r"(b[1]));
}

// ============================================================================
// TF32 GEMM: C[m,n] = sum_k A[m,k] * W[n,k]   (i.e. A @ W^T)
// M=4096, N=1024, K=1024. Block tile 128x128x32, 8 warps (2M x 4N),
// warp tile 64x32 -> 4 Mtiles x 4 Ntiles of m16n8k8.
// blockIdx.z selects (W, C). Optional fused RoPE epilogue (z < ropeCount).
// ============================================================================
__global__ __launch_bounds__(256)
void gemm_tf32(const float* __restrict__ A,
               const float* __restrict__ W0, const float* __restrict__ W1,
               const float* __restrict__ W2,
               float* __restrict__ C0, float* __restrict__ C1, float* __restrict__ C2,
               const int* __restrict__ tokpos, int ropeCount)
{
    const float* W = W0; float* C = C0;
    if (blockIdx.z == 1) { W = W1; C = C1; }
    else if (blockIdx.z == 2) { W = W2; C = C2; }
    const bool do_rope = ((int)blockIdx.z) < ropeCount;

    __shared__ __align__(16) float Xs[128][36];
    __shared__ __align__(16) float Ws[128][36];

    const int tid  = threadIdx.x;
    const int lane = tid & 31;
    const int warp = tid >> 5;
    const int wm = warp >> 2;   // 0..1
    const int wn = warp & 3;    // 0..3
    const int g = lane >> 2;    // 0..7
    const int c = lane & 3;     // 0..3
    const int m0 = blockIdx.y * 128;
    const int n0 = blockIdx.x * 128;

    float acc[4][4][4];
    #pragma unroll
    for (int i = 0; i < 4; i++)
        #pragma unroll
        for (int j = 0; j < 4; j++)
            #pragma unroll
            for (int r = 0; r < 4; r++) acc[i][j][r] = 0.f;

    for (int k0 = 0; k0 < D_MOD; k0 += 32) {
        #pragma unroll
        for (int p = 0; p < 4; p++) {
            int i   = tid + p * 256;
            int row = i >> 3;            // 8 float4 per 32-wide row
            int c4  = (i & 7) << 2;
            float4 va = *(const float4*)(A + (size_t)(m0 + row) * D_MOD + k0 + c4);
            uint4 ta = make_uint4(f2tf(va.x), f2tf(va.y), f2tf(va.z), f2tf(va.w));
            *(uint4*)(&Xs[row][c4]) = ta;
            float4 vb = *(const float4*)(W + (size_t)(n0 + row) * D_MOD + k0 + c4);
            uint4 tb = make_uint4(f2tf(vb.x), f2tf(vb.y), f2tf(vb.z), f2tf(vb.w));
            *(uint4*)(&Ws[row][c4]) = tb;
        }
        __syncthreads();
        #pragma unroll
        for (int ks = 0; ks < 4; ks++) {
            unsigned a[4][4], b[4][2];
            #pragma unroll
            for (int mt = 0; mt < 4; mt++) {
                int rb = wm * 64 + mt * 16;
                a[mt][0] = __float_as_uint(Xs[rb + g    ][ks * 8 + c    ]);
                a[mt][1] = __float_as_uint(Xs[rb + g + 8][ks * 8 + c    ]);
                a[mt][2] = __float_as_uint(Xs[rb + g    ][ks * 8 + c + 4]);
                a[mt][3] = __float_as_uint(Xs[rb + g + 8][ks * 8 + c + 4]);
            }
            #pragma unroll
            for (int nt = 0; nt < 4; nt++) {
                int nb = wn * 32 + nt * 8;
                b[nt][0] = __float_as_uint(Ws[nb + g][ks * 8 + c    ]);
                b[nt][1] = __float_as_uint(Ws[nb + g][ks * 8 + c + 4]);
            }
            #pragma unroll
            for (int mt = 0; mt < 4; mt++)
                #pragma unroll
                for (int nt = 0; nt < 4; nt++)
                    mma8(acc[mt][nt], a[mt], b[nt]);
        }
        __syncthreads();
    }

    // Epilogue (+ optional RoPE over full-D pairs (2j, 2j+1))
    #pragma unroll
    for (int mt = 0; mt < 4; mt++) {
        int r0 = m0 + wm * 64 + mt * 16 + g;
        int r1 = r0 + 8;
        int p0 = 0, p1 = 0;
        if (do_rope) { p0 = tokpos[r0]; p1 = tokpos[r1]; }
        #pragma unroll
        for (int nt = 0; nt < 4; nt++) {
            int col = n0 + wn * 32 + nt * 8 + c * 2;
            float x00 = acc[mt][nt][0], x01 = acc[mt][nt][1];
            float x10 = acc[mt][nt][2], x11 = acc[mt][nt][3];
            if (do_rope) {
                // inv_freq = theta^(-col/1024); compute in double for accuracy.
                float freq = (float)exp2((double)col * (-13.287712379549449 / 1024.0));
                float s0, cs0, s1, cs1;
                sincosf((float)p0 * freq, &s0, &cs0);
                sincosf((float)p1 * freq, &s1, &cs1);
                float y00 = x00 * cs0 - x01 * s0, y01 = x00 * s0 + x01 * cs0;
                float y10 = x10 * cs1 - x11 * s1, y11 = x10 * s1 + x11 * cs1;
                x00 = y00; x01 = y01; x10 = y10; x11 = y11;
            }
            *(float2*)(C + (size_t)r0 * D_MOD + col) = make_float2(x00, x01);
            *(float2*)(C + (size_t)r1 * D_MOD + col) = make_float2(x10, x11);
        }
    }
}

// ============================================================================
// Fused causal flash attention, tf32 mma for QK^T and PV, fp32 online softmax.
// Block: 64 queries of one (b,h); 4 warps, each warp owns 16 query rows.
// grid = (S/64 = 32, B*H = 32).
// ============================================================================
#define QK_STR 68
#define V_STR  72
#define SM_Q 0
#define SM_K (64 * QK_STR)                       // 4352
#define SM_V (2 * 64 * QK_STR)                   // 8704
#define SM_P (2 * 64 * QK_STR + 64 * V_STR)      // 13312
#define FLASH_SMEM_FLOATS (SM_P + 64 * QK_STR)   // 17664
#define FLASH_SMEM_BYTES  (FLASH_SMEM_FLOATS * 4)

__global__ __launch_bounds__(128)
void flash_attn()
{
    extern __shared__ __align__(16) float sm[];
    const int tid  = threadIdx.x;
    const int lane = tid & 31;
    const int warp = tid >> 5;   // 0..3
    const int g = lane >> 2;
    const int c = lane & 3;
    const int qt = blockIdx.x;        // query tile 0..31
    const int bh = blockIdx.y;
    const int b = bh >> 4, h = bh & 15;

    const size_t base = ((size_t)b * S_LEN) * D_MOD + (size_t)h * DK;
    const float* Qg = g_Q + base + (size_t)qt * 64 * D_MOD;

    // Load Q tile (64x64), pre-scaled by 1/sqrt(dk) = 0.125 (exact power of 2)
    #pragma unroll
    for (int p = 0; p < 8; p++) {
        int i  = tid + p * 128;
        int r  = i >> 4;
        int c4 = (i & 15) << 2;
        float4 v = *(const float4*)(Qg + (size_t)r * D_MOD + c4);
        uint4 t = make_uint4(f2tf(v.x * 0.125f), f2tf(v.y * 0.125f),
                             f2tf(v.z * 0.125f), f2tf(v.w * 0.125f));
        *(uint4*)(&sm[SM_Q + r * QK_STR + c4]) = t;
    }

    float m0f = -CUDART_INF_F, m1f = -CUDART_INF_F;
    float l0 = 0.f, l1 = 0.f;
    float o[8][4];
    #pragma unroll
    for (int dt = 0; dt < 8; dt++)
        #pragma unroll
        for (int r = 0; r < 4; r++) o[dt][r] = 0.f;

    const int qrow0 = warp * 16 + g;  // local query row (0..63)
    const int qrow1 = qrow0 + 8;

    for (int kt = 0; kt <= qt; kt++) {
        __syncthreads();
        const float* Kg = g_K + base + (size_t)kt * 64 * D_MOD;
        const float* Vg = g_V + base + (size_t)kt * 64 * D_MOD;
        #pragma unroll
        for (int p = 0; p < 8; p++) {
            int i  = tid + p * 128;
            int r  = i >> 4;
            int c4 = (i & 15) << 2;
            float4 vk = *(const float4*)(Kg + (size_t)r * D_MOD + c4);
            uint4 tk = make_uint4(f2tf(vk.x), f2tf(vk.y), f2tf(vk.z), f2tf(vk.w));
            *(uint4*)(&sm[SM_K + r * QK_STR + c4]) = tk;
            float4 vv = *(const float4*)(Vg + (size_t)r * D_MOD + c4);
            uint4 tv = make_uint4(f2tf(vv.x), f2tf(vv.y), f2tf(vv.z), f2tf(vv.w));
            *(uint4*)(&sm[SM_V + r * V_STR + c4]) = tv;
        }
        __syncthreads();

        // S = Q @ K^T  (scaled): 16q x 64k per warp
        float sacc[8][4];
        #pragma unroll
        for (int nt = 0; nt < 8; nt++)
            #pragma unroll
            for (int r = 0; r < 4; r++) sacc[nt][r] = 0.f;

        #pragma unroll
        for (int ks = 0; ks < 8; ks++) {
            unsigned a[4];
            a[0] = __float_as_uint(sm[SM_Q + (warp * 16 + g    ) * QK_STR + ks * 8 + c    ]);
            a[1] = __float_as_uint(sm[SM_Q + (warp * 16 + g + 8) * QK_STR + ks * 8 + c    ]);
            a[2] = __float_as_uint(sm[SM_Q + (warp * 16 + g    ) * QK_STR + ks * 8 + c + 4]);
            a[3] = __float_as_uint(sm[SM_Q + (warp * 16 + g + 8) * QK_STR + ks * 8 + c + 4]);
            #pragma unroll
            for (int nt = 0; nt < 8; nt++) {
                unsigned bf[2];
                bf[0] = __float_as_uint(sm[SM_K + (nt * 8 + g) * QK_STR + ks * 8 + c    ]);
                bf[1] = __float_as_uint(sm[SM_K + (nt * 8 + g) * QK_STR + ks * 8 + c + 4]);
                mma8(sacc[nt], a, bf);
            }
        }

        // Causal mask (only the diagonal tile is partially masked)
        if (kt == qt) {
            #pragma unroll
            for (int nt = 0; nt < 8; nt++) {
                int k0c = nt * 8 + c * 2, k1c = k0c + 1;
                if (k0c > qrow0) sacc[nt][0] = -CUDART_INF_F;
                if (k1c > qrow0) sacc[nt][1] = -CUDART_INF_F;
                if (k0c > qrow1) sacc[nt][2] = -CUDART_INF_F;
                if (k1c > qrow1) sacc[nt][3] = -CUDART_INF_F;
            }
        }

        // Online softmax (per query row; quad of lanes shares a row)
        float r0 = -CUDART_INF_F, r1 = -CUDART_INF_F;
        #pragma unroll
        for (int nt = 0; nt < 8; nt++) {
            r0 = fmaxf(r0, fmaxf(sacc[nt][0], sacc[nt][1]));
            r1 = fmaxf(r1, fmaxf(sacc[nt][2], sacc[nt][3]));
        }
        r0 = fmaxf(r0, __shfl_xor_sync(0xffffffffu, r0, 1));
        r0 = fmaxf(r0, __shfl_xor_sync(0xffffffffu, r0, 2));
        r1 = fmaxf(r1, __shfl_xor_sync(0xffffffffu, r1, 1));
        r1 = fmaxf(r1, __shfl_xor_sync(0xffffffffu, r1, 2));
        float mn0 = fmaxf(m0f, r0), mn1 = fmaxf(m1f, r1);
        float al0 = __expf(m0f - mn0), al1 = __expf(m1f - mn1);
        m0f = mn0; m1f = mn1;

        float rs0 = 0.f, rs1 = 0.f;
        #pragma unroll
        for (int nt = 0; nt < 8; nt++) {
            float p00 = __expf(sacc[nt][0] - mn0);
            float p01 = __expf(sacc[nt][1] - mn0);
            float p10 = __expf(sacc[nt][2] - mn1);
            float p11 = __expf(sacc[nt][3] - mn1);
            rs0 += p00 + p01; rs1 += p10 + p11;
            int colb = nt * 8 + c * 2;
            sm[SM_P + qrow0 * QK_STR + colb    ] = __uint_as_float(f2tf(p00));
            sm[SM_P + qrow0 * QK_STR + colb + 1] = __uint_as_float(f2tf(p01));
            sm[SM_P + qrow1 * QK_STR + colb    ] = __uint_as_float(f2tf(p10));
            sm[SM_P + qrow1 * QK_STR + colb + 1] = __uint_as_float(f2tf(p11));
        }
        l0 = l0 * al0 + rs0;
        l1 = l1 * al1 + rs1;
        #pragma unroll
        for (int dt = 0; dt < 8; dt++) {
            o[dt][0] *= al0; o[dt][1] *= al0;
            o[dt][2] *= al1; o[dt][3] *= al1;
        }
        __syncwarp();

        // O += P @ V   (16q x 64d per warp; k-dim = 64 keys)
        #pragma unroll
        for (int ks = 0; ks < 8; ks++) {
            unsigned a[4];
            a[0] = __float_as_uint(sm[SM_P + (warp * 16 + g    ) * QK_STR + ks * 8 + c    ]);
            a[1] = __float_as_uint(sm[SM_P + (warp * 16 + g + 8) * QK_STR + ks * 8 + c    ]);
            a[2] = __float_as_uint(sm[SM_P + (warp * 16 + g    ) * QK_STR + ks * 8 + c + 4]);
            a[3] = __float_as_uint(sm[SM_P + (warp * 16 + g + 8) * QK_STR + ks * 8 + c + 4]);
            #pragma unroll
            for (int dt = 0; dt < 8; dt++) {
                unsigned bf[2];
                bf[0] = __float_as_uint(sm[SM_V + (ks * 8 + c    ) * V_STR + dt * 8 + g]);
                bf[1] = __float_as_uint(sm[SM_V + (ks * 8 + c + 4) * V_STR + dt * 8 + g]);
                mma8(o[dt], a, bf);
            }
        }
    }

    // Finalize: reduce l over the quad, divide, write out (head-interleaved)
    l0 += __shfl_xor_sync(0xffffffffu, l0, 1);
    l0 += __shfl_xor_sync(0xffffffffu, l0, 2);
    l1 += __shfl_xor_sync(0xffffffffu, l1, 1);
    l1 += __shfl_xor_sync(0xffffffffu, l1, 2);
    float inv0 = 1.f / l0, inv1 = 1.f / l1;

    float* Og = g_AO + base + (size_t)qt * 64 * D_MOD;
    #pragma unroll
    for (int dt = 0; dt < 8; dt++) {
        int colb = dt * 8 + c * 2;
        *(float2*)(Og + (size_t)qrow0 * D_MOD + colb) =
            make_float2(o[dt][0] * inv0, o[dt][1] * inv0);
        *(float2*)(Og + (size_t)qrow1 * D_MOD + colb) =
            make_float2(o[dt][2] * inv1, o[dt][3] * inv1);
    }
}

// ============================================================================
extern "C" void kernel_launch(void* const* d_in, const int* in_sizes, int n_in,
                              void* d_out, int out_size)
{
    (void)in_sizes; (void)n_in; (void)out_size;
    const float* x  = (const float*)d_in[0];
    const int*   tp = (const int*)d_in[1];
    const float* wq = (const float*)d_in[2];
    const float* wk = (const float*)d_in[3];
    const float* wv = (const float*)d_in[4];
    const float* wo = (const float*)d_in[5];
    float* out = (float*)d_out;

    float *qptr, *kptr, *vptr, *aoptr;
    cudaGetSymbolAddress((void**)&qptr, g_Q);
    cudaGetSymbolAddress((void**)&kptr, g_K);
    cudaGetSymbolAddress((void**)&vptr, g_V);
    cudaGetSymbolAddress((void**)&aoptr, g_AO);

    cudaFuncSetAttribute(flash_attn, cudaFuncAttributeMaxDynamicSharedMemorySize,
                         FLASH_SMEM_BYTES);

    // Q/K/V projections (+ fused RoPE on Q and K)
    dim3 gq(D_MOD / 128, M_TOT / 128, 3);
    gemm_tf32<<<gq, 256>>>(x, wq, wk, wv, qptr, kptr, vptr, tp, 2);

    // Fused causal attention
    flash_attn<<<dim3(S_LEN / 64, B_SZ * NH), 128, FLASH_SMEM_BYTES>>>();

    // Output projection
    dim3 go(D_MOD / 128, M_TOT / 128, 1);
    gemm_tf32<<<go, 256>>>(aoptr, wo, wo, wo, out, out, out, nullptr, 0);
}

// round 2
// speedup vs baseline: 1.1536x; 1.1536x over previous
#include <cuda_runtime.h>
#include <math.h>
#include <math_constants.h>

#define B_SZ   2
#define S_LEN  2048
#define D_MOD  1024
#define NH     16
#define DK     64
#define M_TOT  (B_SZ * S_LEN)   // 4096

// Scratch (allocation-free rule: __device__ globals)
__device__ float g_Q[M_TOT * D_MOD];
__device__ float g_K[M_TOT * D_MOD];
__device__ float g_V[M_TOT * D_MOD];
__device__ float g_AO[M_TOT * D_MOD];

__device__ __forceinline__ unsigned f2tf(float f) {
    unsigned u;
    asm("cvt.rna.tf32.f32 %0, %1;" : "=r"(u) : "f"(f));
    return u;
}

__device__ __forceinline__ void mma8(float* d, const unsigned* a, const unsigned* b) {
    asm volatile(
        "mma.sync.aligned.m16n8k8.row.col.f32.tf32.tf32.f32 "
        "{%0,%1,%2,%3}, {%4,%5,%6,%7}, {%8,%9}, {%0,%1,%2,%3};\n"
        : "+f"(d[0]), "+f"(d[1]), "+f"(d[2]), "+f"(d[3])
        : "r"(a[0]), "r"(a[1]), "r"(a[2]), "r"(a[3]), "r"(b[0]), "r"(b[1]));
}

__device__ __forceinline__ void cp16(float* smem, const float* gmem) {
    unsigned s = (unsigned)__cvta_generic_to_shared(smem);
    asm volatile("cp.async.cg.shared.global [%0], [%1], 16;" :: "r"(s), "l"(gmem));
}
#define CP_COMMIT() asm volatile("cp.async.commit_group;")
#define CP_WAIT1()  asm volatile("cp.async.wait_group 1;")

// ============================================================================
// TF32 GEMM: C[m,n] = sum_k A[m,k] * W[n,k]   (i.e. A @ W^T)
// M=4096, N=1024, K=1024. Block tile 128x128x32, 8 warps (2M x 4N),
// warp tile 64x32 -> 4 Mtiles x 4 Ntiles of m16n8k8.
// cp.async double-buffered mainloop; tf32 convert at consumer (RNA rounding).
// blockIdx.z selects (W, C). Optional fused RoPE epilogue (z < ropeCount).
// ============================================================================
#define GSTG   9216            // floats per stage: (128*36)*2
#define GEMM_SMEM_BYTES (2 * GSTG * 4)   // 73728

__global__ __launch_bounds__(256, 2)
void gemm_tf32(const float* __restrict__ A,
               const float* __restrict__ W0, const float* __restrict__ W1,
               const float* __restrict__ W2,
               float* __restrict__ C0, float* __restrict__ C1, float* __restrict__ C2,
               const int* __restrict__ tokpos, int ropeCount)
{
    const float* W = W0; float* C = C0;
    if (blockIdx.z == 1) { W = W1; C = C1; }
    else if (blockIdx.z == 2) { W = W2; C = C2; }
    const bool do_rope = ((int)blockIdx.z) < ropeCount;

    extern __shared__ __align__(16) float sm_g[];

    const int tid  = threadIdx.x;
    const int lane = tid & 31;
    const int warp = tid >> 5;
    const int wm = warp >> 2;   // 0..1
    const int wn = warp & 3;    // 0..3
    const int g = lane >> 2;    // 0..7
    const int c = lane & 3;     // 0..3
    const int m0 = blockIdx.y * 128;
    const int n0 = blockIdx.x * 128;

    // Per-thread copy coordinates (8 float4s per 32-col row)
    const int crow = tid >> 3;
    const int cc4  = (tid & 7) << 2;

    float acc[4][4][4];
    #pragma unroll
    for (int i = 0; i < 4; i++)
        #pragma unroll
        for (int j = 0; j < 4; j++)
            #pragma unroll
            for (int r = 0; r < 4; r++) acc[i][j][r] = 0.f;

    // ---- prologue: stage 0 copy ----
    {
        float* Xs = sm_g;
        float* Ws = sm_g + 4608;
        #pragma unroll
        for (int p = 0; p < 4; p++) {
            int row = crow + p * 32;
            cp16(&Xs[row * 36 + cc4], A + (size_t)(m0 + row) * D_MOD + cc4);
            cp16(&Ws[row * 36 + cc4], W + (size_t)(n0 + row) * D_MOD + cc4);
        }
        CP_COMMIT();
    }

    const int NIT = D_MOD / 32;   // 32
    for (int it = 0; it < NIT; it++) {
        // prefetch next stage
        if (it + 1 < NIT) {
            int nb = (it + 1) & 1;
            int k0 = (it + 1) * 32;
            float* Xs = sm_g + nb * GSTG;
            float* Ws = Xs + 4608;
            #pragma unroll
            for (int p = 0; p < 4; p++) {
                int row = crow + p * 32;
                cp16(&Xs[row * 36 + cc4], A + (size_t)(m0 + row) * D_MOD + k0 + cc4);
                cp16(&Ws[row * 36 + cc4], W + (size_t)(n0 + row) * D_MOD + k0 + cc4);
            }
        }
        CP_COMMIT();
        CP_WAIT1();
        __syncthreads();

        const float* Xs = sm_g + (it & 1) * GSTG;
        const float* Ws = Xs + 4608;

        #pragma unroll
        for (int ks = 0; ks < 4; ks++) {
            unsigned a[4][4], b[4][2];
            #pragma unroll
            for (int mt = 0; mt < 4; mt++) {
                int rb = wm * 64 + mt * 16;
                a[mt][0] = f2tf(Xs[(rb + g    ) * 36 + ks * 8 + c    ]);
                a[mt][1] = f2tf(Xs[(rb + g + 8) * 36 + ks * 8 + c    ]);
                a[mt][2] = f2tf(Xs[(rb + g    ) * 36 + ks * 8 + c + 4]);
                a[mt][3] = f2tf(Xs[(rb + g + 8) * 36 + ks * 8 + c + 4]);
            }
            #pragma unroll
            for (int nt = 0; nt < 4; nt++) {
                int nb2 = wn * 32 + nt * 8;
                b[nt][0] = f2tf(Ws[(nb2 + g) * 36 + ks * 8 + c    ]);
                b[nt][1] = f2tf(Ws[(nb2 + g) * 36 + ks * 8 + c + 4]);
            }
            #pragma unroll
            for (int mt = 0; mt < 4; mt++)
                #pragma unroll
                for (int nt = 0; nt < 4; nt++)
                    mma8(acc[mt][nt], a[mt], b[nt]);
        }
        __syncthreads();   // protect this buffer from the prefetch 2 iters ahead
    }

    // Epilogue (+ optional RoPE over full-D pairs (2j, 2j+1))
    #pragma unroll
    for (int mt = 0; mt < 4; mt++) {
        int r0 = m0 + wm * 64 + mt * 16 + g;
        int r1 = r0 + 8;
        int p0 = 0, p1 = 0;
        if (do_rope) { p0 = tokpos[r0]; p1 = tokpos[r1]; }
        #pragma unroll
        for (int nt = 0; nt < 4; nt++) {
            int col = n0 + wn * 32 + nt * 8 + c * 2;
            float x00 = acc[mt][nt][0], x01 = acc[mt][nt][1];
            float x10 = acc[mt][nt][2], x11 = acc[mt][nt][3];
            if (do_rope) {
                // inv_freq = theta^(-col/1024); compute in double for accuracy.
                float freq = (float)exp2((double)col * (-13.287712379549449 / 1024.0));
                float s0, cs0, s1, cs1;
                sincosf((float)p0 * freq, &s0, &cs0);
                sincosf((float)p1 * freq, &s1, &cs1);
                float y00 = x00 * cs0 - x01 * s0, y01 = x00 * s0 + x01 * cs0;
                float y10 = x10 * cs1 - x11 * s1, y11 = x10 * s1 + x11 * cs1;
                x00 = y00; x01 = y01; x10 = y10; x11 = y11;
            }
            *(float2*)(C + (size_t)r0 * D_MOD + col) = make_float2(x00, x01);
            *(float2*)(C + (size_t)r1 * D_MOD + col) = make_float2(x10, x11);
        }
    }
}

// ============================================================================
// Fused causal flash attention, tf32 mma for QK^T and PV, fp32 online softmax.
// Block: 64 queries of one (b,h); 4 warps, each warp owns 16 query rows.
// grid = (S/64 = 32, B*H = 32).
// ============================================================================
#define QK_STR 68
#define V_STR  72
#define SM_Q 0
#define SM_K (64 * QK_STR)                       // 4352
#define SM_V (2 * 64 * QK_STR)                   // 8704
#define SM_P (2 * 64 * QK_STR + 64 * V_STR)      // 13312
#define FLASH_SMEM_FLOATS (SM_P + 64 * QK_STR)   // 17664
#define FLASH_SMEM_BYTES  (FLASH_SMEM_FLOATS * 4)

__global__ __launch_bounds__(128)
void flash_attn()
{
    extern __shared__ __align__(16) float sm[];
    const int tid  = threadIdx.x;
    const int lane = tid & 31;
    const int warp = tid >> 5;   // 0..3
    const int g = lane >> 2;
    const int c = lane & 3;
    const int qt = blockIdx.x;        // query tile 0..31
    const int bh = blockIdx.y;
    const int b = bh >> 4, h = bh & 15;

    const size_t base = ((size_t)b * S_LEN) * D_MOD + (size_t)h * DK;
    const float* Qg = g_Q + base + (size_t)qt * 64 * D_MOD;

    // Load Q tile (64x64), pre-scaled by 1/sqrt(dk) = 0.125 (exact power of 2)
    #pragma unroll
    for (int p = 0; p < 8; p++) {
        int i  = tid + p * 128;
        int r  = i >> 4;
        int c4 = (i & 15) << 2;
        float4 v = *(const float4*)(Qg + (size_t)r * D_MOD + c4);
        uint4 t = make_uint4(f2tf(v.x * 0.125f), f2tf(v.y * 0.125f),
                             f2tf(v.z * 0.125f), f2tf(v.w * 0.125f));
        *(uint4*)(&sm[SM_Q + r * QK_STR + c4]) = t;
    }

    float m0f = -CUDART_INF_F, m1f = -CUDART_INF_F;
    float l0 = 0.f, l1 = 0.f;
    float o[8][4];
    #pragma unroll
    for (int dt = 0; dt < 8; dt++)
        #pragma unroll
        for (int r = 0; r < 4; r++) o[dt][r] = 0.f;

    const int qrow0 = warp * 16 + g;  // local query row (0..63)
    const int qrow1 = qrow0 + 8;

    for (int kt = 0; kt <= qt; kt++) {
        __syncthreads();
        const float* Kg = g_K + base + (size_t)kt * 64 * D_MOD;
        const float* Vg = g_V + base + (size_t)kt * 64 * D_MOD;
        #pragma unroll
        for (int p = 0; p < 8; p++) {
            int i  = tid + p * 128;
            int r  = i >> 4;
            int c4 = (i & 15) << 2;
            float4 vk = *(const float4*)(Kg + (size_t)r * D_MOD + c4);
            uint4 tk = make_uint4(f2tf(vk.x), f2tf(vk.y), f2tf(vk.z), f2tf(vk.w));
            *(uint4*)(&sm[SM_K + r * QK_STR + c4]) = tk;
            float4 vv = *(const float4*)(Vg + (size_t)r * D_MOD + c4);
            uint4 tv = make_uint4(f2tf(vv.x), f2tf(vv.y), f2tf(vv.z), f2tf(vv.w));
            *(uint4*)(&sm[SM_V + r * V_STR + c4]) = tv;
        }
        __syncthreads();

        // S = Q @ K^T  (scaled): 16q x 64k per warp
        float sacc[8][4];
        #pragma unroll
        for (int nt = 0; nt < 8; nt++)
            #pragma unroll
            for (int r = 0; r < 4; r++) sacc[nt][r] = 0.f;

        #pragma unroll
        for (int ks = 0; ks < 8; ks++) {
            unsigned a[4];
            a[0] = __float_as_uint(sm[SM_Q + (warp * 16 + g    ) * QK_STR + ks * 8 + c    ]);
            a[1] = __float_as_uint(sm[SM_Q + (warp * 16 + g + 8) * QK_STR + ks * 8 + c    ]);
            a[2] = __float_as_uint(sm[SM_Q + (warp * 16 + g    ) * QK_STR + ks * 8 + c + 4]);
            a[3] = __float_as_uint(sm[SM_Q + (warp * 16 + g + 8) * QK_STR + ks * 8 + c + 4]);
            #pragma unroll
            for (int nt = 0; nt < 8; nt++) {
                unsigned bf[2];
                bf[0] = __float_as_uint(sm[SM_K + (nt * 8 + g) * QK_STR + ks * 8 + c    ]);
                bf[1] = __float_as_uint(sm[SM_K + (nt * 8 + g) * QK_STR + ks * 8 + c + 4]);
                mma8(sacc[nt], a, bf);
            }
        }

        // Causal mask (only the diagonal tile is partially masked)
        if (kt == qt) {
            #pragma unroll
            for (int nt = 0; nt < 8; nt++) {
                int k0c = nt * 8 + c * 2, k1c = k0c + 1;
                if (k0c > qrow0) sacc[nt][0] = -CUDART_INF_F;
                if (k1c > qrow0) sacc[nt][1] = -CUDART_INF_F;
                if (k0c > qrow1) sacc[nt][2] = -CUDART_INF_F;
                if (k1c > qrow1) sacc[nt][3] = -CUDART_INF_F;
            }
        }

        // Online softmax (per query row; quad of lanes shares a row)
        float r0 = -CUDART_INF_F, r1 = -CUDART_INF_F;
        #pragma unroll
        for (int nt = 0; nt < 8; nt++) {
            r0 = fmaxf(r0, fmaxf(sacc[nt][0], sacc[nt][1]));
            r1 = fmaxf(r1, fmaxf(sacc[nt][2], sacc[nt][3]));
        }
        r0 = fmaxf(r0, __shfl_xor_sync(0xffffffffu, r0, 1));
        r0 = fmaxf(r0, __shfl_xor_sync(0xffffffffu, r0, 2));
        r1 = fmaxf(r1, __shfl_xor_sync(0xffffffffu, r1, 1));
        r1 = fmaxf(r1, __shfl_xor_sync(0xffffffffu, r1, 2));
        float mn0 = fmaxf(m0f, r0), mn1 = fmaxf(m1f, r1);
        float al0 = __expf(m0f - mn0), al1 = __expf(m1f - mn1);
        m0f = mn0; m1f = mn1;

        float rs0 = 0.f, rs1 = 0.f;
        #pragma unroll
        for (int nt = 0; nt < 8; nt++) {
            float p00 = __expf(sacc[nt][0] - mn0);
            float p01 = __expf(sacc[nt][1] - mn0);
            float p10 = __expf(sacc[nt][2] - mn1);
            float p11 = __expf(sacc[nt][3] - mn1);
            rs0 += p00 + p01; rs1 += p10 + p11;
            int colb = nt * 8 + c * 2;
            sm[SM_P + qrow0 * QK_STR + colb    ] = __uint_as_float(f2tf(p00));
            sm[SM_P + qrow0 * QK_STR + colb + 1] = __uint_as_float(f2tf(p01));
            sm[SM_P + qrow1 * QK_STR + colb    ] = __uint_as_float(f2tf(p10));
            sm[SM_P + qrow1 * QK_STR + colb + 1] = __uint_as_float(f2tf(p11));
        }
        l0 = l0 * al0 + rs0;
        l1 = l1 * al1 + rs1;
        #pragma unroll
        for (int dt = 0; dt < 8; dt++) {
            o[dt][0] *= al0; o[dt][1] *= al0;
            o[dt][2] *= al1; o[dt][3] *= al1;
        }
        __syncwarp();

        // O += P @ V   (16q x 64d per warp; k-dim = 64 keys)
        #pragma unroll
        for (int ks = 0; ks < 8; ks++) {
            unsigned a[4];
            a[0] = __float_as_uint(sm[SM_P + (warp * 16 + g    ) * QK_STR + ks * 8 + c    ]);
            a[1] = __float_as_uint(sm[SM_P + (warp * 16 + g + 8) * QK_STR + ks * 8 + c    ]);
            a[2] = __float_as_uint(sm[SM_P + (warp * 16 + g    ) * QK_STR + ks * 8 + c + 4]);
            a[3] = __float_as_uint(sm[SM_P + (warp * 16 + g + 8) * QK_STR + ks * 8 + c + 4]);
            #pragma unroll
            for (int dt = 0; dt < 8; dt++) {
                unsigned bf[2];
                bf[0] = __float_as_uint(sm[SM_V + (ks * 8 + c    ) * V_STR + dt * 8 + g]);
                bf[1] = __float_as_uint(sm[SM_V + (ks * 8 + c + 4) * V_STR + dt * 8 + g]);
                mma8(o[dt], a, bf);
            }
        }
    }

    // Finalize: reduce l over the quad, divide, write out (head-interleaved)
    l0 += __shfl_xor_sync(0xffffffffu, l0, 1);
    l0 += __shfl_xor_sync(0xffffffffu, l0, 2);
    l1 += __shfl_xor_sync(0xffffffffu, l1, 1);
    l1 += __shfl_xor_sync(0xffffffffu, l1, 2);
    float inv0 = 1.f / l0, inv1 = 1.f / l1;

    float* Og = g_AO + base + (size_t)qt * 64 * D_MOD;
    #pragma unroll
    for (int dt = 0; dt < 8; dt++) {
        int colb = dt * 8 + c * 2;
        *(float2*)(Og + (size_t)qrow0 * D_MOD + colb) =
            make_float2(o[dt][0] * inv0, o[dt][1] * inv0);
        *(float2*)(Og + (size_t)qrow1 * D_MOD + colb) =
            make_float2(o[dt][2] * inv1, o[dt][3] * inv1);
    }
}

// ============================================================================
extern "C" void kernel_launch(void* const* d_in, const int* in_sizes, int n_in,
                              void* d_out, int out_size)
{
    (void)in_sizes; (void)n_in; (void)out_size;
    const float* x  = (const float*)d_in[0];
    const int*   tp = (const int*)d_in[1];
    const float* wq = (const float*)d_in[2];
    const float* wk = (const float*)d_in[3];
    const float* wv = (const float*)d_in[4];
    const float* wo = (const float*)d_in[5];
    float* out = (float*)d_out;

    float *qptr, *kptr, *vptr, *aoptr;
    cudaGetSymbolAddress((void**)&qptr, g_Q);
    cudaGetSymbolAddress((void**)&kptr, g_K);
    cudaGetSymbolAddress((void**)&vptr, g_V);
    cudaGetSymbolAddress((void**)&aoptr, g_AO);

    cudaFuncSetAttribute(gemm_tf32, cudaFuncAttributeMaxDynamicSharedMemorySize,
                         GEMM_SMEM_BYTES);
    cudaFuncSetAttribute(flash_attn, cudaFuncAttributeMaxDynamicSharedMemorySize,
                         FLASH_SMEM_BYTES);

    // Q/K/V projections (+ fused RoPE on Q and K)
    dim3 gq(D_MOD / 128, M_TOT / 128, 3);
    gemm_tf32<<<gq, 256, GEMM_SMEM_BYTES>>>(x, wq, wk, wv, qptr, kptr, vptr, tp, 2);

    // Fused causal attention
    flash_attn<<<dim3(S_LEN / 64, B_SZ * NH), 128, FLASH_SMEM_BYTES>>>();

    // Output projection
    dim3 go(D_MOD / 128, M_TOT / 128, 1);
    gemm_tf32<<<go, 256, GEMM_SMEM_BYTES>>>(aoptr, wo, wo, wo, out, out, out, nullptr, 0);
}

// round 3
// speedup vs baseline: 1.3439x; 1.1649x over previous
#include <cuda_runtime.h>
#include <math.h>
#include <math_constants.h>

#define B_SZ   2
#define S_LEN  2048
#define D_MOD  1024
#define NH     16
#define DK     64
#define M_TOT  (B_SZ * S_LEN)   // 4096

// Scratch (allocation-free rule: __device__ globals)
__device__ float g_X [M_TOT * D_MOD];   // x, tf32-rounded + k-permuted
__device__ float g_Wq[D_MOD * D_MOD];
__device__ float g_Wk[D_MOD * D_MOD];
__device__ float g_Wv[D_MOD * D_MOD];
__device__ float g_Wo[D_MOD * D_MOD];
__device__ float g_Q [M_TOT * D_MOD];   // rounded, col-permuted
__device__ float g_K [M_TOT * D_MOD];   // rounded, col-permuted
__device__ float g_VT[M_TOT * D_MOD];   // V transposed [b,h,d',s'], rounded
__device__ float g_AO[M_TOT * D_MOD];   // attention out, rounded, k-permuted

__device__ __forceinline__ unsigned f2tf(float f) {
    unsigned u;
    asm("cvt.rna.tf32.f32 %0, %1;" : "=r"(u) : "f"(f));
    return u;
}
__device__ __forceinline__ float rtf(float f) { return __uint_as_float(f2tf(f)); }

__device__ __forceinline__ void mma8(float* d, const unsigned* a, const unsigned* b) {
    asm volatile(
        "mma.sync.aligned.m16n8k8.row.col.f32.tf32.tf32.f32 "
        "{%0,%1,%2,%3}, {%4,%5,%6,%7}, {%8,%9}, {%0,%1,%2,%3};\n"
        : "+f"(d[0]), "+f"(d[1]), "+f"(d[2]), "+f"(d[3])
        : "r"(a[0]), "r"(a[1]), "r"(a[2]), "r"(a[3]), "r"(b[0]), "r"(b[1]));
}

__device__ __forceinline__ void cp16(float* smem, const float* gmem) {
    unsigned s = (unsigned)__cvta_generic_to_shared(smem);
    asm volatile("cp.async.cg.shared.global [%0], [%1], 16;" :: "r"(s), "l"(gmem));
}
#define CP_COMMIT() asm volatile("cp.async.commit_group;")
#define CP_WAIT0()  asm volatile("cp.async.wait_group 0;")

// ============================================================================
// Pre-round + k-permute: tf32 RNA rounding, and every 8-k group reordered to
// [k0,k4,k1,k5,k2,k6,k3,k7] so fragment pairs (c, c+4) sit adjacent (LDS.64).
// Segments: x (524288 groups), wq/wk/wv/wo (131072 groups each) = 1048576.
// ============================================================================
__global__ __launch_bounds__(256)
void preround(const float* __restrict__ x,
              const float* __restrict__ wq, const float* __restrict__ wk,
              const float* __restrict__ wv, const float* __restrict__ wo)
{
    int gidx = blockIdx.x * blockDim.x + threadIdx.x;   // group id
    const float* src; float* dst; int off;
    if (gidx < 524288) { src = x; dst = g_X; off = gidx; }
    else {
        int t = gidx - 524288; int w = t >> 17; off = t & 131071;
        src = (w == 0) ? wq : (w == 1) ? wk : (w == 2) ? wv : wo;
        dst = (w == 0) ? g_Wq : (w == 1) ? g_Wk : (w == 2) ? g_Wv : g_Wo;
    }
    float4 a = ((const float4*)src)[off * 2];       // k0..k3
    float4 b = ((const float4*)src)[off * 2 + 1];   // k4..k7
    float4 o1 = make_float4(rtf(a.x), rtf(b.x), rtf(a.y), rtf(b.y));
    float4 o2 = make_float4(rtf(a.z), rtf(b.z), rtf(a.w), rtf(b.w));
    ((float4*)dst)[off * 2]     = o1;
    ((float4*)dst)[off * 2 + 1] = o2;
}

// ============================================================================
// TF32 GEMM: C = A @ W^T, inputs pre-rounded & k-permuted (no cvt in loop).
// 128x128x32 tiles, 8 warps, LDS.64 fragment loads, one __syncthreads/iter.
// mode 0 (QKV): z<2 -> RoPE + round + col-permute; z==2 -> V transpose store.
// mode 1: plain output (final projection).
// ============================================================================
#define SROW 40
#define GSTG (128 * SROW * 2)                 // 10240 floats per stage
#define GEMM_SMEM_BYTES (2 * GSTG * 4)        // 81920

__global__ __launch_bounds__(256, 2)
void gemm_tf32(const float* __restrict__ A,
               const float* __restrict__ W0, const float* __restrict__ W1,
               const float* __restrict__ W2,
               float* __restrict__ C0, float* __restrict__ C1, float* __restrict__ C2,
               const int* __restrict__ tokpos, int mode)
{
    const float* W = W0; float* C = C0;
    if (blockIdx.z == 1) { W = W1; C = C1; }
    else if (blockIdx.z == 2) { W = W2; C = C2; }

    extern __shared__ __align__(16) float sm_g[];

    const int tid  = threadIdx.x;
    const int lane = tid & 31;
    const int warp = tid >> 5;
    const int wm = warp >> 2;   // 0..1
    const int wn = warp & 3;    // 0..3
    const int g = lane >> 2;    // 0..7
    const int c = lane & 3;     // 0..3
    const int m0 = blockIdx.y * 128;
    const int n0 = blockIdx.x * 128;

    const int crow = tid >> 3;
    const int cc4  = (tid & 7) << 2;

    float acc[4][4][4];
    #pragma unroll
    for (int i = 0; i < 4; i++)
        #pragma unroll
        for (int j = 0; j < 4; j++)
            #pragma unroll
            for (int r = 0; r < 4; r++) acc[i][j][r] = 0.f;

    // prologue: stage 0
    {
        float* Xs = sm_g;
        float* Ws = sm_g + 128 * SROW;
        #pragma unroll
        for (int p = 0; p < 4; p++) {
            int row = crow + p * 32;
            cp16(&Xs[row * SROW + cc4], A + (size_t)(m0 + row) * D_MOD + cc4);
            cp16(&Ws[row * SROW + cc4], W + (size_t)(n0 + row) * D_MOD + cc4);
        }
        CP_COMMIT();
    }

    const int NIT = D_MOD / 32;
    for (int it = 0; it < NIT; it++) {
        CP_WAIT0();
        __syncthreads();
        if (it + 1 < NIT) {
            int k0 = (it + 1) * 32;
            float* Xs = sm_g + ((it + 1) & 1) * GSTG;
            float* Ws = Xs + 128 * SROW;
            #pragma unroll
            for (int p = 0; p < 4; p++) {
                int row = crow + p * 32;
                cp16(&Xs[row * SROW + cc4], A + (size_t)(m0 + row) * D_MOD + k0 + cc4);
                cp16(&Ws[row * SROW + cc4], W + (size_t)(n0 + row) * D_MOD + k0 + cc4);
            }
            CP_COMMIT();
        }

        const float* Xs = sm_g + (it & 1) * GSTG;
        const float* Ws = Xs + 128 * SROW;

        #pragma unroll
        for (int ks = 0; ks < 4; ks++) {
            unsigned a[4][4], b[4][2];
            #pragma unroll
            for (int mt = 0; mt < 4; mt++) {
                int rb = wm * 64 + mt * 16;
                float2 v0 = *(const float2*)&Xs[(rb + g    ) * SROW + ks * 8 + 2 * c];
                float2 v1 = *(const float2*)&Xs[(rb + g + 8) * SROW + ks * 8 + 2 * c];
                a[mt][0] = __float_as_uint(v0.x);
                a[mt][1] = __float_as_uint(v1.x);
                a[mt][2] = __float_as_uint(v0.y);
                a[mt][3] = __float_as_uint(v1.y);
            }
            #pragma unroll
            for (int nt = 0; nt < 4; nt++) {
                float2 vb = *(const float2*)&Ws[(wn * 32 + nt * 8 + g) * SROW + ks * 8 + 2 * c];
                b[nt][0] = __float_as_uint(vb.x);
                b[nt][1] = __float_as_uint(vb.y);
            }
            #pragma unroll
            for (int mt = 0; mt < 4; mt++)
                #pragma unroll
                for (int nt = 0; nt < 4; nt++)
                    mma8(acc[mt][nt], a[mt], b[nt]);
        }
    }
    __syncthreads();

    // in-group permuted position of col offset 2c: (0,4,1,5 for c=0..3)
    const int qoff = ((2 * c) & 3) * 2 + (c >> 1);

    #pragma unroll
    for (int mt = 0; mt < 4; mt++) {
        int r0 = m0 + wm * 64 + mt * 16 + g;
        int r1 = r0 + 8;
        if (mode == 1) {
            #pragma unroll
            for (int nt = 0; nt < 4; nt++) {
                int col = n0 + wn * 32 + nt * 8 + c * 2;
                *(float2*)(C + (size_t)r0 * D_MOD + col) = make_float2(acc[mt][nt][0], acc[mt][nt][1]);
                *(float2*)(C + (size_t)r1 * D_MOD + col) = make_float2(acc[mt][nt][2], acc[mt][nt][3]);
            }
        } else if (blockIdx.z < 2) {
            // RoPE (true cols) + round + permuted store
            int p0 = tokpos[r0], p1 = tokpos[r1];
            #pragma unroll
            for (int nt = 0; nt < 4; nt++) {
                int colgrp = n0 + wn * 32 + nt * 8;
                int col = colgrp + c * 2;
                float x00 = acc[mt][nt][0], x01 = acc[mt][nt][1];
                float x10 = acc[mt][nt][2], x11 = acc[mt][nt][3];
                float freq = (float)exp2((double)col * (-13.287712379549449 / 1024.0));
                float s0, cs0, s1, cs1;
                sincosf((float)p0 * freq, &s0, &cs0);
                sincosf((float)p1 * freq, &s1, &cs1);
                float y00 = x00 * cs0 - x01 * s0, y01 = x00 * s0 + x01 * cs0;
                float y10 = x10 * cs1 - x11 * s1, y11 = x10 * s1 + x11 * cs1;
                C[(size_t)r0 * D_MOD + colgrp + qoff    ] = rtf(y00);
                C[(size_t)r0 * D_MOD + colgrp + qoff + 2] = rtf(y01);
                C[(size_t)r1 * D_MOD + colgrp + qoff    ] = rtf(y10);
                C[(size_t)r1 * D_MOD + colgrp + qoff + 2] = rtf(y11);
            }
        } else {
            // V: transposed store  g_VT[((b*16+h)*64 + d')*2048 + s']
            int bb = r0 >> 11;
            int s0i = r0 & 2047;
            int sq = (s0i & ~7) | (((s0i & 3) << 1) | ((s0i >> 2) & 1));
            #pragma unroll
            for (int nt = 0; nt < 4; nt++) {
                int colgrp = n0 + wn * 32 + nt * 8;
                int n = colgrp + 2 * c;
                int h = n >> 6, d = n & 63;
                int dq = (d & ~7) + qoff;
                size_t o = ((size_t)((bb << 4) | h) * 64 + dq) * 2048 + sq;
                C[o           ] = rtf(acc[mt][nt][0]);
                C[o + 4096    ] = rtf(acc[mt][nt][1]);   // d'+2
                C[o + 8       ] = rtf(acc[mt][nt][2]);   // s'+8 (row r1)
                C[o + 4096 + 8] = rtf(acc[mt][nt][3]);
            }
        }
    }
}

// ============================================================================
// Fused causal flash attention. Pre-rounded, k-permuted Q/K; V transposed.
// Q fragments hoisted to registers; K/V^T cp.async double-buffered.
// Block: 64 queries of one (b,h); 4 warps. grid = (32, 32).
// ============================================================================
#define KSTR 72
#define FS_Q 0                         // 64x72 (reused as P after hoist)
#define FS_K 4608                      // + stage*4608
#define FS_V (4608 + 2*4608)           // + stage*4608
#define FLASH_SMEM_BYTES (4608 * 5 * 4)  // 92160

__global__ __launch_bounds__(128)
void flash_attn()
{
    extern __shared__ __align__(16) float sm[];
    const int tid  = threadIdx.x;
    const int lane = tid & 31;
    const int warp = tid >> 5;   // 0..3
    const int g = lane >> 2;
    const int c = lane & 3;
    const int qt = (S_LEN / 64 - 1) - blockIdx.x;   // heavy tiles first
    const int bh = blockIdx.y;
    const int b = bh >> 4, h = bh & 15;

    const float* Qg  = g_Q  + ((size_t)(b * S_LEN + qt * 64)) * D_MOD + h * 64;
    const float* Kg  = g_K  + ((size_t)(b * S_LEN)) * D_MOD + h * 64;
    const float* VTg = g_VT + ((size_t)((b * 16 + h) * 64)) * 2048;

    const int crow = tid >> 4;          // 0..7
    const int cc4  = (tid & 15) << 2;   // 0..60

    // prologue: cp.async K/V^T stage 0 (kt = 0)
    #pragma unroll
    for (int p = 0; p < 8; p++) {
        int row = crow + p * 8;
        cp16(&sm[FS_K + row * KSTR + cc4], Kg  + (size_t)row * D_MOD + cc4);
        cp16(&sm[FS_V + row * KSTR + cc4], VTg + (size_t)row * 2048 + cc4);
    }
    CP_COMMIT();

    // Q tile load (scale by 1/8, exact) into FS_Q
    #pragma unroll
    for (int p = 0; p < 8; p++) {
        int row = crow + p * 8;
        float4 v = *(const float4*)(Qg + (size_t)row * D_MOD + cc4);
        v.x *= 0.125f; v.y *= 0.125f; v.z *= 0.125f; v.w *= 0.125f;
        *(float4*)(&sm[FS_Q + row * KSTR + cc4]) = v;
    }
    __syncthreads();

    // hoist Q fragments (32 regs); FS_Q becomes P after first loop sync
    unsigned qa[8][4];
    #pragma unroll
    for (int ks = 0; ks < 8; ks++) {
        float2 v0 = *(const float2*)&sm[FS_Q + (warp * 16 + g    ) * KSTR + ks * 8 + 2 * c];
        float2 v1 = *(const float2*)&sm[FS_Q + (warp * 16 + g + 8) * KSTR + ks * 8 + 2 * c];
        qa[ks][0] = __float_as_uint(v0.x);
        qa[ks][1] = __float_as_uint(v1.x);
        qa[ks][2] = __float_as_uint(v0.y);
        qa[ks][3] = __float_as_uint(v1.y);
    }

    float m0f = -CUDART_INF_F, m1f = -CUDART_INF_F;
    float l0 = 0.f, l1 = 0.f;
    float o[8][4];
    #pragma unroll
    for (int dt = 0; dt < 8; dt++)
        #pragma unroll
        for (int r = 0; r < 4; r++) o[dt][r] = 0.f;

    const int qrow0 = warp * 16 + g;
    const int qrow1 = qrow0 + 8;
    const int qoff  = ((2 * c) & 3) * 2 + (c >> 1);

    for (int kt = 0; kt <= qt; kt++) {
        CP_WAIT0();
        __syncthreads();
        if (kt < qt) {
            int st = (kt + 1) & 1;
            #pragma unroll
            for (int p = 0; p < 8; p++) {
                int row = crow + p * 8;
                cp16(&sm[FS_K + st * 4608 + row * KSTR + cc4],
                     Kg + (size_t)((kt + 1) * 64 + row) * D_MOD + cc4);
                cp16(&sm[FS_V + st * 4608 + row * KSTR + cc4],
                     VTg + (size_t)row * 2048 + (kt + 1) * 64 + cc4);
            }
            CP_COMMIT();
        }
        const float* Ks = sm + FS_K + (kt & 1) * 4608;
        const float* Vs = sm + FS_V + (kt & 1) * 4608;

        // S = Q @ K^T
        float sacc[8][4];
        #pragma unroll
        for (int nt = 0; nt < 8; nt++)
            #pragma unroll
            for (int r = 0; r < 4; r++) sacc[nt][r] = 0.f;

        #pragma unroll
        for (int ks = 0; ks < 8; ks++) {
            #pragma unroll
            for (int nt = 0; nt < 8; nt++) {
                float2 kb = *(const float2*)&Ks[(nt * 8 + g) * KSTR + ks * 8 + 2 * c];
                unsigned bf[2] = { __float_as_uint(kb.x), __float_as_uint(kb.y) };
                mma8(sacc[nt], qa[ks], bf);
            }
        }

        // causal mask (diagonal tile only); key cols are true indices
        if (kt == qt) {
            #pragma unroll
            for (int nt = 0; nt < 8; nt++) {
                int k0c = nt * 8 + c * 2, k1c = k0c + 1;
                if (k0c > qrow0) sacc[nt][0] = -CUDART_INF_F;
                if (k1c > qrow0) sacc[nt][1] = -CUDART_INF_F;
                if (k0c > qrow1) sacc[nt][2] = -CUDART_INF_F;
                if (k1c > qrow1) sacc[nt][3] = -CUDART_INF_F;
            }
        }

        // online softmax
        float r0 = -CUDART_INF_F, r1 = -CUDART_INF_F;
        #pragma unroll
        for (int nt = 0; nt < 8; nt++) {
            r0 = fmaxf(r0, fmaxf(sacc[nt][0], sacc[nt][1]));
            r1 = fmaxf(r1, fmaxf(sacc[nt][2], sacc[nt][3]));
        }
        r0 = fmaxf(r0, __shfl_xor_sync(0xffffffffu, r0, 1));
        r0 = fmaxf(r0, __shfl_xor_sync(0xffffffffu, r0, 2));
        r1 = fmaxf(r1, __shfl_xor_sync(0xffffffffu, r1, 1));
        r1 = fmaxf(r1, __shfl_xor_sync(0xffffffffu, r1, 2));
        float mn0 = fmaxf(m0f, r0), mn1 = fmaxf(m1f, r1);
        float al0 = __expf(m0f - mn0), al1 = __expf(m1f - mn1);
        m0f = mn0; m1f = mn1;

        float rs0 = 0.f, rs1 = 0.f;
        #pragma unroll
        for (int nt = 0; nt < 8; nt++) {
            float p00 = __expf(sacc[nt][0] - mn0);
            float p01 = __expf(sacc[nt][1] - mn0);
            float p10 = __expf(sacc[nt][2] - mn1);
            float p11 = __expf(sacc[nt][3] - mn1);
            rs0 += p00 + p01; rs1 += p10 + p11;
            // P stored at key-permuted positions (matches V^T col permutation)
            int pb = nt * 8 + qoff;
            sm[FS_Q + qrow0 * KSTR + pb    ] = rtf(p00);
            sm[FS_Q + qrow0 * KSTR + pb + 2] = rtf(p01);
            sm[FS_Q + qrow1 * KSTR + pb    ] = rtf(p10);
            sm[FS_Q + qrow1 * KSTR + pb + 2] = rtf(p11);
        }
        l0 = l0 * al0 + rs0;
        l1 = l1 * al1 + rs1;
        #pragma unroll
        for (int dt = 0; dt < 8; dt++) {
            o[dt][0] *= al0; o[dt][1] *= al0;
            o[dt][2] *= al1; o[dt][3] *= al1;
        }
        __syncwarp();

        // O += P @ V  (V^T rows = dk, cols = keys; both k-pairs via LDS.64)
        #pragma unroll
        for (int ks = 0; ks < 8; ks++) {
            float2 pa0 = *(const float2*)&sm[FS_Q + qrow0 * KSTR + ks * 8 + 2 * c];
            float2 pa1 = *(const float2*)&sm[FS_Q + qrow1 * KSTR + ks * 8 + 2 * c];
            unsigned a[4] = { __float_as_uint(pa0.x), __float_as_uint(pa1.x),
                              __float_as_uint(pa0.y), __float_as_uint(pa1.y) };
            #pragma unroll
            for (int dt = 0; dt < 8; dt++) {
                float2 vb = *(const float2*)&Vs[(dt * 8 + g) * KSTR + ks * 8 + 2 * c];
                unsigned bf[2] = { __float_as_uint(vb.x), __float_as_uint(vb.y) };
                mma8(o[dt], a, bf);
            }
        }
        __syncwarp();   // P reads done before next iter's P writes
    }

    l0 += __shfl_xor_sync(0xffffffffu, l0, 1);
    l0 += __shfl_xor_sync(0xffffffffu, l0, 2);
    l1 += __shfl_xor_sync(0xffffffffu, l1, 1);
    l1 += __shfl_xor_sync(0xffffffffu, l1, 2);
    float inv0 = 1.f / l0, inv1 = 1.f / l1;

    float* Og = g_AO + ((size_t)(b * S_LEN + qt * 64)) * D_MOD + h * 64;
    #pragma unroll
    for (int dt = 0; dt < 8; dt++) {
        int colb = dt * 8 + c * 2;
        *(float2*)(Og + (size_t)qrow0 * D_MOD + colb) =
            make_float2(rtf(o[dt][0] * inv0), rtf(o[dt][1] * inv0));
        *(float2*)(Og + (size_t)qrow1 * D_MOD + colb) =
            make_float2(rtf(o[dt][2] * inv1), rtf(o[dt][3] * inv1));
    }
}

// ============================================================================
extern "C" void kernel_launch(void* const* d_in, const int* in_sizes, int n_in,
                              void* d_out, int out_size)
{
    (void)in_sizes; (void)n_in; (void)out_size;
    const float* x  = (const float*)d_in[0];
    const int*   tp = (const int*)d_in[1];
    const float* wq = (const float*)d_in[2];
    const float* wk = (const float*)d_in[3];
    const float* wv = (const float*)d_in[4];
    const float* wo = (const float*)d_in[5];
    float* out = (float*)d_out;

    float *xptr, *wqp, *wkp, *wvp, *wop, *qptr, *kptr, *vtptr, *aoptr;
    cudaGetSymbolAddress((void**)&xptr,  g_X);
    cudaGetSymbolAddress((void**)&wqp,   g_Wq);
    cudaGetSymbolAddress((void**)&wkp,   g_Wk);
    cudaGetSymbolAddress((void**)&wvp,   g_Wv);
    cudaGetSymbolAddress((void**)&wop,   g_Wo);
    cudaGetSymbolAddress((void**)&qptr,  g_Q);
    cudaGetSymbolAddress((void**)&kptr,  g_K);
    cudaGetSymbolAddress((void**)&vtptr, g_VT);
    cudaGetSymbolAddress((void**)&aoptr, g_AO);

    cudaFuncSetAttribute(gemm_tf32, cudaFuncAttributeMaxDynamicSharedMemorySize,
                         GEMM_SMEM_BYTES);
    cudaFuncSetAttribute(flash_attn, cudaFuncAttributeMaxDynamicSharedMemorySize,
                         FLASH_SMEM_BYTES);

    // 0) round inputs to tf32 + k-permute
    preround<<<4096, 256>>>(x, wq, wk, wv, wo);

    // 1) Q/K/V projections (+ fused RoPE on Q,K; V stored transposed)
    dim3 gq(D_MOD / 128, M_TOT / 128, 3);
    gemm_tf32<<<gq, 256, GEMM_SMEM_BYTES>>>(xptr, wqp, wkp, wvp,
                                            qptr, kptr, vtptr, tp, 0);

    // 2) fused causal attention
    flash_attn<<<dim3(S_LEN / 64, B_SZ * NH), 128, FLASH_SMEM_BYTES>>>();

    // 3) output projection (plain epilogue)
    dim3 go(D_MOD / 128, M_TOT / 128, 1);
    gemm_tf32<<<go, 256, GEMM_SMEM_BYTES>>>(aoptr, wop, wop, wop,
                                            out, out, out, nullptr, 1);
}